// round 1
// baseline (speedup 1.0000x reference)
#include <cuda_runtime.h>
#include <math.h>

// ---------------------------------------------------------------------------
// PADigitalTwin: 5-tap Volterra memory polynomial (orders 1,3,5,7) + global
// noise-floor calibration + phase-noise rotation + AWGN.
//
// Shapes (fixed by the dataset):
//   x           [16, 131072, 2] f32
//   coeffs_real [4, 5]          f32
//   coeffs_imag [4, 5]          f32
//   awgn        [16, 131068, 2] f32
//   phase_noise [16, 131068]    f32
//   out         [16, 131068, 2] f32
// ---------------------------------------------------------------------------

#define MEMD      5
#define SLEN      131072
#define OUTLEN    131068          // SLEN - MEMD + 1
#define BATCH     16
#define TPT       4               // outputs per thread
#define JOBS_PB   (OUTLEN / TPT)  // 32767
#define TOTAL_JOBS (BATCH * JOBS_PB)       // 524272
#define BLOCK     256
#define GRID1     ((TOTAL_JOBS + BLOCK - 1) / BLOCK)  // 2048

__device__ float g_partials[GRID1];
__device__ float g_noise_std;

// Compute yr/yi for 4 consecutive outputs starting at n0 = j*4 of batch-row xb4.
// Window: output n uses samples n..n+4; tap m multiplies sample n+4-m.
__device__ __forceinline__ void volterra4(const float4* __restrict__ xb4, int j,
                                          const float cr[4][5], const float ci[4][5],
                                          float yr[TPT], float yi[TPT])
{
    float I[8], Q[8], a2[8], a4[8], a6[8];
#pragma unroll
    for (int v = 0; v < 4; v++) {
        float4 p = __ldg(&xb4[j * 2 + v]);   // two complex samples per float4
        I[2 * v]     = p.x;  Q[2 * v]     = p.y;
        I[2 * v + 1] = p.z;  Q[2 * v + 1] = p.w;
    }
#pragma unroll
    for (int s = 0; s < 8; s++) {
        a2[s] = fmaf(I[s], I[s], Q[s] * Q[s]);
        a4[s] = a2[s] * a2[s];
        a6[s] = a4[s] * a2[s];
    }
#pragma unroll
    for (int o = 0; o < TPT; o++) {
        float sr = 0.f, si = 0.f;
#pragma unroll
        for (int m = 0; m < MEMD; m++) {
            int w = o + (MEMD - 1) - m;     // window index of sample n0+o+4-m
            float fr = fmaf(cr[3][m], a6[w],
                       fmaf(cr[2][m], a4[w],
                       fmaf(cr[1][m], a2[w], cr[0][m])));
            float fi = fmaf(ci[3][m], a6[w],
                       fmaf(ci[2][m], a4[w],
                       fmaf(ci[1][m], a2[w], ci[0][m])));
            sr = fmaf(fr, I[w], fmaf(-fi, Q[w], sr));
            si = fmaf(fr, Q[w], fmaf( fi, I[w], si));
        }
        yr[o] = sr;
        yi[o] = si;
    }
}

__device__ __forceinline__ void load_coeffs(const float* __restrict__ crg,
                                            const float* __restrict__ cig,
                                            float cr[4][5], float ci[4][5])
{
#pragma unroll
    for (int k = 0; k < 4; k++)
#pragma unroll
        for (int m = 0; m < 5; m++) {
            cr[k][m] = __ldg(&crg[k * 5 + m]);
            ci[k][m] = __ldg(&cig[k * 5 + m]);
        }
}

// ---------------- Pass 1: per-block partial sums of yr^2 + yi^2 -------------
__global__ __launch_bounds__(BLOCK)
void pa_pass1(const float* __restrict__ x,
              const float* __restrict__ crg,
              const float* __restrict__ cig)
{
    float cr[4][5], ci[4][5];
    load_coeffs(crg, cig, cr, ci);

    int tid = blockIdx.x * BLOCK + threadIdx.x;
    float acc = 0.f;
    if (tid < TOTAL_JOBS) {
        int b = tid / JOBS_PB;
        int j = tid - b * JOBS_PB;
        const float4* xb4 = (const float4*)(x + (size_t)b * SLEN * 2);
        float yr[TPT], yi[TPT];
        volterra4(xb4, j, cr, ci, yr, yi);
#pragma unroll
        for (int o = 0; o < TPT; o++)
            acc = fmaf(yr[o], yr[o], fmaf(yi[o], yi[o], acc));
    }

    // block reduce (deterministic: fixed tree)
    __shared__ float sh[BLOCK / 32];
#pragma unroll
    for (int off = 16; off > 0; off >>= 1)
        acc += __shfl_down_sync(0xffffffffu, acc, off);
    if ((threadIdx.x & 31) == 0) sh[threadIdx.x >> 5] = acc;
    __syncthreads();
    if (threadIdx.x < BLOCK / 32) {
        float v = sh[threadIdx.x];
#pragma unroll
        for (int off = (BLOCK / 32) / 2; off > 0; off >>= 1)
            v += __shfl_down_sync(0xffu, v, off);
        if (threadIdx.x == 0) g_partials[blockIdx.x] = v;
    }
}

// ---------------- Pass 2: final reduce -> noise_std -------------------------
__global__ __launch_bounds__(256)
void pa_reduce()
{
    __shared__ double sh[256];
    double s = 0.0;
    for (int i = threadIdx.x; i < GRID1; i += 256)
        s += (double)g_partials[i];
    sh[threadIdx.x] = s;
    __syncthreads();
#pragma unroll
    for (int off = 128; off > 0; off >>= 1) {
        if (threadIdx.x < off) sh[threadIdx.x] += sh[threadIdx.x + off];
        __syncthreads();
    }
    if (threadIdx.x == 0) {
        double mean = sh[0] / ((double)BATCH * (double)OUTLEN);
        double signal_power = mean * 0.5;
        g_noise_std = (float)sqrt(signal_power * 1.0e-6);  // 10^(-60/10)
    }
}

// ---------------- Pass 3: recompute + rotate + add noise --------------------
__global__ __launch_bounds__(BLOCK)
void pa_pass3(const float* __restrict__ x,
              const float* __restrict__ crg,
              const float* __restrict__ cig,
              const float* __restrict__ awgn,
              const float* __restrict__ pn,
              float* __restrict__ out)
{
    float cr[4][5], ci[4][5];
    load_coeffs(crg, cig, cr, ci);

    int tid = blockIdx.x * BLOCK + threadIdx.x;
    if (tid >= TOTAL_JOBS) return;
    int b = tid / JOBS_PB;
    int j = tid - b * JOBS_PB;

    const float4* xb4 = (const float4*)(x + (size_t)b * SLEN * 2);
    float yr[TPT], yi[TPT];
    volterra4(xb4, j, cr, ci, yr, yi);

    float ns = g_noise_std;

    const float4* pn4 = (const float4*)(pn + (size_t)b * OUTLEN);
    float4 p = __ldg(&pn4[j]);
    float prad[TPT] = {p.x, p.y, p.z, p.w};

    const float4* aw4 = (const float4*)(awgn + (size_t)b * OUTLEN * 2);
    float4 aw0 = __ldg(&aw4[j * 2]);
    float4 aw1 = __ldg(&aw4[j * 2 + 1]);

    const float KRAD = 0.008726646259971648f;   // 0.5 * pi / 180
    float yrc[TPT], yic[TPT];
#pragma unroll
    for (int o = 0; o < TPT; o++) {
        float c, s;
        __sincosf(prad[o] * KRAD, &s, &c);
        yrc[o] = yr[o] * c - yi[o] * s;
        yic[o] = yr[o] * s + yi[o] * c;
    }

    float4 o0, o1;
    o0.x = fmaf(aw0.x, ns, yrc[0]);  o0.y = fmaf(aw0.y, ns, yic[0]);
    o0.z = fmaf(aw0.z, ns, yrc[1]);  o0.w = fmaf(aw0.w, ns, yic[1]);
    o1.x = fmaf(aw1.x, ns, yrc[2]);  o1.y = fmaf(aw1.y, ns, yic[2]);
    o1.z = fmaf(aw1.z, ns, yrc[3]);  o1.w = fmaf(aw1.w, ns, yic[3]);

    float4* out4 = (float4*)(out + (size_t)b * OUTLEN * 2);
    out4[j * 2]     = o0;
    out4[j * 2 + 1] = o1;
}

// ---------------------------------------------------------------------------
extern "C" void kernel_launch(void* const* d_in, const int* in_sizes, int n_in,
                              void* d_out, int out_size)
{
    const float* x    = (const float*)d_in[0];
    const float* cr   = (const float*)d_in[1];
    const float* ci   = (const float*)d_in[2];
    const float* awgn = (const float*)d_in[3];
    const float* pn   = (const float*)d_in[4];
    float* out        = (float*)d_out;

    pa_pass1<<<GRID1, BLOCK>>>(x, cr, ci);
    pa_reduce<<<1, 256>>>();
    pa_pass3<<<GRID1, BLOCK>>>(x, cr, ci, awgn, pn, out);
}

// round 2
// speedup vs baseline: 1.0841x; 1.0841x over previous
#include <cuda_runtime.h>
#include <math.h>

// ---------------------------------------------------------------------------
// PADigitalTwin: 5-tap Volterra memory polynomial (orders 1,3,5,7) + global
// noise-floor calibration + phase-noise rotation + AWGN.
//
//   x           [16, 131072, 2] f32
//   coeffs_real [4, 5]          f32
//   coeffs_imag [4, 5]          f32
//   awgn        [16, 131068, 2] f32
//   phase_noise [16, 131068]    f32
//   out         [16, 131068, 2] f32
//
// Structure: pa_main (Volterra once -> scratch y in L2 + power partials),
// pa_reduce (noise_std), pa_epi (streaming rotate+noise epilogue).
// ---------------------------------------------------------------------------

#define MEMD      5
#define SLEN      131072
#define OUTLEN    131068          // SLEN - MEMD + 1
#define BATCH     16
#define TPT       4               // outputs per thread
#define JOBS_PB   (OUTLEN / TPT)  // 32767 (exact)
#define BLOCK     256
#define GRIDX     ((JOBS_PB + BLOCK - 1) / BLOCK)   // 128
#define NPART     (GRIDX * BATCH)                   // 2048

__constant__ float c_cr[20];      // [k][m], k-major (k*5+m)
__constant__ float c_ci[20];

__device__ float g_y[(size_t)BATCH * OUTLEN * 2];   // 16.8 MB scratch (L2-resident)
__device__ float g_partials[NPART];
__device__ float g_noise_std;

// ---------------- Pass 1: Volterra -> g_y, power partials -------------------
__global__ __launch_bounds__(BLOCK)
void pa_main(const float* __restrict__ x)
{
    const int j = blockIdx.x * BLOCK + threadIdx.x;
    const int b = blockIdx.y;
    float acc = 0.f;

    if (j < JOBS_PB) {
        const float4* xb4 = (const float4*)(x + (size_t)b * SLEN * 2);
        float I[8], Q[8], a2[8];
#pragma unroll
        for (int v = 0; v < 4; v++) {
            float4 p = __ldg(&xb4[j * 2 + v]);   // two complex samples / float4
            I[2 * v]     = p.x;  Q[2 * v]     = p.y;
            I[2 * v + 1] = p.z;  Q[2 * v + 1] = p.w;
        }
#pragma unroll
        for (int s = 0; s < 8; s++)
            a2[s] = fmaf(I[s], I[s], Q[s] * Q[s]);

        float yr[TPT], yi[TPT];
#pragma unroll
        for (int o = 0; o < TPT; o++) {
            float sr = 0.f, si = 0.f;
#pragma unroll
            for (int m = 0; m < MEMD; m++) {
                const int w = o + (MEMD - 1) - m;
                const float e = a2[w];
                // envelope polys: Horner in |x|^2
                float fr = fmaf(fmaf(fmaf(c_cr[15 + m], e, c_cr[10 + m]), e,
                                     c_cr[5 + m]), e, c_cr[m]);
                float fi = fmaf(fmaf(fmaf(c_ci[15 + m], e, c_ci[10 + m]), e,
                                     c_ci[5 + m]), e, c_ci[m]);
                sr = fmaf(fr, I[w], fmaf(-fi, Q[w], sr));
                si = fmaf(fr, Q[w], fmaf( fi, I[w], si));
            }
            yr[o] = sr;
            yi[o] = si;
            acc = fmaf(sr, sr, fmaf(si, si, acc));
        }

        float4* y4 = (float4*)(g_y + (size_t)b * OUTLEN * 2);
        float4 s0, s1;
        s0.x = yr[0]; s0.y = yi[0]; s0.z = yr[1]; s0.w = yi[1];
        s1.x = yr[2]; s1.y = yi[2]; s1.z = yr[3]; s1.w = yi[3];
        y4[j * 2]     = s0;
        y4[j * 2 + 1] = s1;
    }

    // deterministic block reduction
    __shared__ float sh[BLOCK / 32];
#pragma unroll
    for (int off = 16; off > 0; off >>= 1)
        acc += __shfl_down_sync(0xffffffffu, acc, off);
    if ((threadIdx.x & 31) == 0) sh[threadIdx.x >> 5] = acc;
    __syncthreads();
    if (threadIdx.x < BLOCK / 32) {
        float v = sh[threadIdx.x];
#pragma unroll
        for (int off = (BLOCK / 32) / 2; off > 0; off >>= 1)
            v += __shfl_down_sync(0xffu, v, off);
        if (threadIdx.x == 0)
            g_partials[blockIdx.y * GRIDX + blockIdx.x] = v;
    }
}

// ---------------- Pass 2: final reduce -> noise_std -------------------------
__global__ __launch_bounds__(256)
void pa_reduce()
{
    __shared__ double sh[256];
    double s = 0.0;
    for (int i = threadIdx.x; i < NPART; i += 256)
        s += (double)g_partials[i];
    sh[threadIdx.x] = s;
    __syncthreads();
#pragma unroll
    for (int off = 128; off > 0; off >>= 1) {
        if (threadIdx.x < off) sh[threadIdx.x] += sh[threadIdx.x + off];
        __syncthreads();
    }
    if (threadIdx.x == 0) {
        double mean = sh[0] / ((double)BATCH * (double)OUTLEN);
        g_noise_std = (float)sqrt(mean * 0.5 * 1.0e-6);   // 10^(-60/10)
    }
}

// ---------------- Pass 3: streaming epilogue --------------------------------
__global__ __launch_bounds__(BLOCK)
void pa_epi(const float* __restrict__ awgn,
            const float* __restrict__ pn,
            float* __restrict__ out)
{
    const int j = blockIdx.x * BLOCK + threadIdx.x;
    if (j >= JOBS_PB) return;
    const int b = blockIdx.y;

    const float4* y4  = (const float4*)(g_y  + (size_t)b * OUTLEN * 2);
    const float4* aw4 = (const float4*)(awgn + (size_t)b * OUTLEN * 2);
    const float4* pn4 = (const float4*)(pn   + (size_t)b * OUTLEN);

    float4 s0 = y4[j * 2];
    float4 s1 = y4[j * 2 + 1];
    float4 p  = __ldg(&pn4[j]);
    float4 a0 = __ldg(&aw4[j * 2]);
    float4 a1 = __ldg(&aw4[j * 2 + 1]);
    const float ns = g_noise_std;

    const float KRAD = 0.008726646259971648f;   // 0.5 * pi / 180
    float c0, sn0, c1, sn1, c2, sn2, c3, sn3;
    __sincosf(p.x * KRAD, &sn0, &c0);
    __sincosf(p.y * KRAD, &sn1, &c1);
    __sincosf(p.z * KRAD, &sn2, &c2);
    __sincosf(p.w * KRAD, &sn3, &c3);

    float4 o0, o1;
    o0.x = fmaf(a0.x, ns, s0.x * c0 - s0.y * sn0);
    o0.y = fmaf(a0.y, ns, s0.x * sn0 + s0.y * c0);
    o0.z = fmaf(a0.z, ns, s0.z * c1 - s0.w * sn1);
    o0.w = fmaf(a0.w, ns, s0.z * sn1 + s0.w * c1);
    o1.x = fmaf(a1.x, ns, s1.x * c2 - s1.y * sn2);
    o1.y = fmaf(a1.y, ns, s1.x * sn2 + s1.y * c2);
    o1.z = fmaf(a1.z, ns, s1.z * c3 - s1.w * sn3);
    o1.w = fmaf(a1.w, ns, s1.z * sn3 + s1.w * c3);

    float4* out4 = (float4*)(out + (size_t)b * OUTLEN * 2);
    out4[j * 2]     = o0;
    out4[j * 2 + 1] = o1;
}

// ---------------------------------------------------------------------------
extern "C" void kernel_launch(void* const* d_in, const int* in_sizes, int n_in,
                              void* d_out, int out_size)
{
    const float* x    = (const float*)d_in[0];
    const float* cr   = (const float*)d_in[1];
    const float* ci   = (const float*)d_in[2];
    const float* awgn = (const float*)d_in[3];
    const float* pn   = (const float*)d_in[4];
    float* out        = (float*)d_out;

    cudaMemcpyToSymbolAsync(c_cr, cr, 20 * sizeof(float), 0,
                            cudaMemcpyDeviceToDevice, 0);
    cudaMemcpyToSymbolAsync(c_ci, ci, 20 * sizeof(float), 0,
                            cudaMemcpyDeviceToDevice, 0);

    dim3 grid(GRIDX, BATCH);
    pa_main<<<grid, BLOCK>>>(x);
    pa_reduce<<<1, 256>>>();
    pa_epi<<<grid, BLOCK>>>(awgn, pn, out);
}